// round 15
// baseline (speedup 1.0000x reference)
#include <cuda_runtime.h>
#include <math.h>

#define N_NODES   15000
#define N_EDGES   60000
#define EDGE_VOCAB 54
#define NODE_INDIM 64
#define EDGE_INDIM 32
#define H  32
#define EH 64
#define NBOND 4
#define NUM_STEPS 3
#define G   148                    // persistent blocks, 1 per SM
#define TPB 1024
#define WPB (TPB / 32)
#define NWARPS (G * WPB)
#define CHUNK ((N_EDGES + G - 1) / G)

// ---------------- device scratch (no allocation allowed) -------------------
__device__ __align__(16) float  g_Wv[EDGE_VOCAB * H * H];
__device__ __align__(16) float  g_h[N_NODES * H];
__device__ __align__(16) float  g_agg[N_NODES * H];
__device__ __align__(16) float4 g_Wpk4[2 * 32 * 32];   // packed GRU weights
__device__ float g_p[N_NODES];
__device__ float g_q[N_NODES];
__device__ float g_nsum[N_NODES];
__device__ int   g_blockcnt[G * 64];
__device__ __align__(8) int2 g_ed[N_EDGES];   // {src | id<<16, dst}, sorted by id
__device__ int           g_bar_count = 0;
__device__ volatile int  g_bar_sense = 0;

// sense-reversing grid barrier; sense is read at kernel entry, so any number
// of barriers per launch is replay-safe.
__device__ __forceinline__ void grid_barrier(int* bsense) {
    __syncthreads();
    if (threadIdx.x == 0) {
        int my = *bsense ^ 1;
        __threadfence();
        if (atomicAdd(&g_bar_count, 1) == G - 1) {
            g_bar_count = 0;
            __threadfence();
            g_bar_sense = my;
        } else {
            while (g_bar_sense != my) { __nanosleep(32); }
        }
        __threadfence();
        *bsense = my;
    }
    __syncthreads();
}

__device__ __forceinline__ float sigmoidf_fast(float x) {
    return __fdividef(1.0f, 1.0f + __expf(-x));
}

__global__ void __launch_bounds__(TPB, 1)
k_fused(const int* __restrict__ node_ids, const int* __restrict__ edge_ids,
        const int* __restrict__ src, const int* __restrict__ dst,
        const float* __restrict__ node_table, const float* __restrict__ edge_table,
        const float* __restrict__ projW, const float* __restrict__ projb,
        const float* __restrict__ attn_w,
        const float* __restrict__ e1W1, const float* __restrict__ e1b1,
        const float* __restrict__ e1W2, const float* __restrict__ e1b2,
        const float* __restrict__ e2W1, const float* __restrict__ e2b1,
        const float* __restrict__ e2W2, const float* __restrict__ e2b2,
        const float* __restrict__ Wih, const float* __restrict__ Whh,
        const float* __restrict__ bih, const float* __restrict__ bhh,
        float* __restrict__ out) {
    __shared__ float S[NODE_INDIM * H];    // proj weights / wvocab tmp (8 KB)
    __shared__ int   SI[64];
    __shared__ int   bsense_sh;

    const int t    = threadIdx.x;
    const int b    = blockIdx.x;
    const int warp = t >> 5;
    const int lane = t & 31;
    const int gwarp = b * WPB + warp;

    if (t == 0) bsense_sh = g_bar_sense;   // adaptive sense: any parity OK
    __syncthreads();
    int bsense = bsense_sh;

    const int ebase = b * CHUNK;
    const int eend  = min(ebase + CHUNK, N_EDGES);

    // ================= phase 0: histogram + vocab W + GRU weight packing ===
    if (t < EDGE_VOCAB) SI[t] = 0;
    __syncthreads();
    for (int e = ebase + t; e < eend; e += TPB) atomicAdd(&SI[edge_ids[e]], 1);
    __syncthreads();
    if (t < EDGE_VOCAB) g_blockcnt[b * 64 + t] = SI[t];

    if (b < EDGE_VOCAB) {   // one block per vocab entry computes its W matrix
        const int v = b;
        const bool bond = (v < NBOND);
        const float* W1 = bond ? e1W1 : e2W1;
        const float* b1 = bond ? e1b1 : e2b1;
        const float* W2 = bond ? e1W2 : e2W2;
        const float* b2 = bond ? e1b2 : e2b2;
        float* ef = S;          // [32]
        float* z  = S + 32;     // [64]
        if (t < EDGE_INDIM) ef[t] = edge_table[v * EDGE_INDIM + t];
        __syncthreads();
        if (t < EH) {
            float acc = b1[t];
            #pragma unroll
            for (int i = 0; i < EDGE_INDIM; i++) acc += ef[i] * W1[t * EDGE_INDIM + i];
            z[t] = fmaxf(acc, 0.0f);
        }
        __syncthreads();
        for (int o = t; o < H * H; o += TPB) {
            float acc = b2[o];
            const float* w = W2 + o * EH;
            #pragma unroll
            for (int k = 0; k < EH; k++) acc += z[k] * w[k];
            g_Wv[v * H * H + o] = acc;
        }
    } else if (b == EDGE_VOCAB) {
        // pack GRU weights: g_Wpk4[m*1024 + k*32 + o] = {W[o][k], W[32+o][k], W[64+o][k], 0}
        for (int f = t; f < 2048; f += TPB) {
            int mm = f >> 10, r = f & 1023, k = r >> 5, o = r & 31;
            const float* Wsrc = mm ? Whh : Wih;
            g_Wpk4[f] = make_float4(Wsrc[o * H + k],
                                    Wsrc[(32 + o) * H + k],
                                    Wsrc[(64 + o) * H + k], 0.0f);
        }
    }
    grid_barrier(&bsense);                                     // B1

    // ====== redundant per-block scan: every block computes its own offsets =
    if (t < EDGE_VOCAB) {
        int tot = 0;
        for (int bb = 0; bb < G; bb++) tot += g_blockcnt[bb * 64 + t];
        SI[t] = tot;          // total size of bucket t
    }
    __syncthreads();
    if (t == 0) {
        int acc = 0;
        for (int v = 0; v < EDGE_VOCAB; v++) { int c = SI[v]; SI[v] = acc; acc += c; }
    }
    __syncthreads();
    if (t < EDGE_VOCAB) {
        int pre = 0;
        for (int bb = 0; bb < b; bb++) pre += g_blockcnt[bb * 64 + t];
        SI[t] = SI[t] + pre;   // this block's scatter cursor for bucket t
    }
    __syncthreads();

    // ================= phase 2: scatter (sort by vocab) + init h ===========
    for (int e = ebase + t; e < eend; e += TPB) {
        int id = edge_ids[e];
        int pos = atomicAdd(&SI[id], 1);
        g_ed[pos] = make_int2(src[e] | (id << 16), dst[e]);
    }
    // init h = relu(nf @ projW^T + b), attention dots, accumulator reset
    {
        for (int idx = t; idx < H * NODE_INDIM; idx += TPB) {
            int o = idx / NODE_INDIM, i = idx % NODE_INDIM;
            S[i * H + o] = projW[idx];
        }
        __syncthreads();
        float aw0 = attn_w[lane], aw1 = attn_w[H + lane];
        for (int v = gwarp; v < N_NODES; v += NWARPS) {
            int nid = node_ids[v];
            const float* nf = node_table + nid * NODE_INDIM;
            float v0 = nf[lane];
            float v1 = nf[lane + 32];
            float acc = projb[lane];
            #pragma unroll
            for (int i = 0; i < 32; i++)
                acc += __shfl_sync(0xffffffffu, v0, i) * S[i * H + lane];
            #pragma unroll
            for (int i = 0; i < 32; i++)
                acc += __shfl_sync(0xffffffffu, v1, i) * S[(i + 32) * H + lane];
            float hv = fmaxf(acc, 0.0f);
            g_h[v * H + lane] = hv;
            g_agg[v * H + lane] = 0.0f;
            float pv = hv * aw0;
            float qv = hv * aw1;
            #pragma unroll
            for (int off = 16; off; off >>= 1) {
                pv += __shfl_down_sync(0xffffffffu, pv, off);
                qv += __shfl_down_sync(0xffffffffu, qv, off);
            }
            if (lane == 0) { g_p[v] = pv; g_q[v] = qv; g_nsum[v] = 0.0f; }
        }
    }
    grid_barrier(&bsense);                                     // B2

    // ================= message passing steps ===============================
    const float b_i0 = bih[lane], b_i1 = bih[32 + lane], b_i2 = bih[64 + lane];
    const float b_h0 = bhh[lane], b_h1 = bhh[32 + lane], b_h2 = bhh[64 + lane];
    const float aw0 = attn_w[lane], aw1 = attn_w[H + lane];

    for (int step = 0; step < NUM_STEPS; step++) {
        // ---- edge phase: warp-per-edge, W in registers, prefetched loads
        {
            int len = eend - ebase;
            int per = (len + WPB - 1) / WPB;
            int w0 = ebase + warp * per;
            int w1 = min(w0 + per, eend);
            int cached = -1;
            float Wr[32];
            if (w0 < w1) {
                // prefetch pipeline: ed/p/q one edge ahead
                int2 ed = g_ed[w0];
                float pn = g_p[ed.x & 0xFFFF];
                float qn = g_q[ed.y];
                for (int pos = w0; pos < w1; pos++) {
                    int2 cur = ed;
                    float pc = pn, qc = qn;
                    if (pos + 1 < w1) {
                        ed = g_ed[pos + 1];
                        pn = g_p[ed.x & 0xFFFF];
                        qn = g_q[ed.y];
                    }
                    int s  = cur.x & 0xFFFF;
                    int id = cur.x >> 16;
                    int d  = cur.y;
                    if (id != cached) {
                        cached = id;
                        const float* Wp = g_Wv + id * (H * H) + lane;
                        #pragma unroll
                        for (int k = 0; k < 32; k++) Wr[k] = Wp[k * 32];
                    }
                    float a = pc + qc;
                    a = (a > 0.0f) ? a : 0.01f * a;        // leaky_relu
                    float ex = __expf(a);                  // shift-free softmax
                    const float4* h4 = (const float4*)(g_h + s * H);
                    float a0 = 0.0f, a1 = 0.0f, a2 = 0.0f, a3 = 0.0f;
                    // ping-pong float4 stream: low reg pressure, MLP=2
                    float4 f0 = h4[0], f1 = h4[1];
                    #pragma unroll
                    for (int j = 0; j < 8; j++) {
                        float4 c = (j & 1) ? f1 : f0;
                        if (j + 2 < 8) { if (j & 1) f1 = h4[j + 2]; else f0 = h4[j + 2]; }
                        a0 = fmaf(c.x, Wr[4 * j + 0], a0);
                        a1 = fmaf(c.y, Wr[4 * j + 1], a1);
                        a2 = fmaf(c.z, Wr[4 * j + 2], a2);
                        a3 = fmaf(c.w, Wr[4 * j + 3], a3);
                    }
                    float acc = ((a0 + a1) + (a2 + a3)) * ex;
                    atomicAdd(&g_agg[d * H + lane], acc);
                    if (lane == 0) atomicAdd(&g_nsum[d], ex);
                }
            }
        }
        grid_barrier(&bsense);                                 // B-edge (x3)

        // ---- GRU phase: 3 nodes per warp, packed float4 weights (L1)
        {
            const int last = (step == NUM_STEPS - 1);
            const float4* __restrict__ Wpk = g_Wpk4;
            for (int v0 = gwarp * 3; v0 < N_NODES; v0 += NWARPS * 3) {
                float m[3], hv[3];
                float gi[3][3], gh[3][3];
                #pragma unroll
                for (int j = 0; j < 3; j++) {
                    int v = min(v0 + j, N_NODES - 1);
                    float ns = g_nsum[v];
                    float inv = (ns > 0.0f) ? __fdividef(1.0f, ns) : 0.0f;
                    m[j]  = fmaxf(g_agg[v * H + lane] * inv, 0.0f);
                    hv[j] = g_h[v * H + lane];
                    gi[j][0] = b_i0; gi[j][1] = b_i1; gi[j][2] = b_i2;
                    gh[j][0] = b_h0; gh[j][1] = b_h1; gh[j][2] = b_h2;
                }
                #pragma unroll
                for (int k = 0; k < 32; k++) {
                    float4 wi = Wpk[k * 32 + lane];
                    float4 wh = Wpk[1024 + k * 32 + lane];
                    #pragma unroll
                    for (int j = 0; j < 3; j++) {
                        float mi = __shfl_sync(0xffffffffu, m[j], k);
                        float hi = __shfl_sync(0xffffffffu, hv[j], k);
                        gi[j][0] = fmaf(mi, wi.x, gi[j][0]);
                        gi[j][1] = fmaf(mi, wi.y, gi[j][1]);
                        gi[j][2] = fmaf(mi, wi.z, gi[j][2]);
                        gh[j][0] = fmaf(hi, wh.x, gh[j][0]);
                        gh[j][1] = fmaf(hi, wh.y, gh[j][1]);
                        gh[j][2] = fmaf(hi, wh.z, gh[j][2]);
                    }
                }
                #pragma unroll
                for (int j = 0; j < 3; j++) {
                    int v = v0 + j;
                    if (v >= N_NODES) break;
                    float r = sigmoidf_fast(gi[j][0] + gh[j][0]);
                    float z = sigmoidf_fast(gi[j][1] + gh[j][1]);
                    float n = tanhf(gi[j][2] + r * gh[j][2]);
                    float hnew = (1.0f - z) * n + z * hv[j];
                    if (last) {
                        out[v * H + lane] = hnew;
                    } else {
                        g_h[v * H + lane] = hnew;
                        g_agg[v * H + lane] = 0.0f;
                        float pv = hnew * aw0;
                        float qv = hnew * aw1;
                        #pragma unroll
                        for (int off = 16; off; off >>= 1) {
                            pv += __shfl_down_sync(0xffffffffu, pv, off);
                            qv += __shfl_down_sync(0xffffffffu, qv, off);
                        }
                        if (lane == 0) { g_p[v] = pv; g_q[v] = qv; g_nsum[v] = 0.0f; }
                    }
                }
            }
        }
        if (step < NUM_STEPS - 1) grid_barrier(&bsense);       // B-gru (x2)
    }
}

// ---------------- launch ----------------------------------------------------
extern "C" void kernel_launch(void* const* d_in, const int* in_sizes, int n_in,
                              void* d_out, int out_size) {
    k_fused<<<G, TPB>>>(
        (const int*)d_in[0], (const int*)d_in[1], (const int*)d_in[2],
        (const int*)d_in[3], (const float*)d_in[4], (const float*)d_in[5],
        (const float*)d_in[6], (const float*)d_in[7], (const float*)d_in[8],
        (const float*)d_in[9], (const float*)d_in[10], (const float*)d_in[11],
        (const float*)d_in[12], (const float*)d_in[13], (const float*)d_in[14],
        (const float*)d_in[15], (const float*)d_in[16], (const float*)d_in[17],
        (const float*)d_in[18], (const float*)d_in[19], (const float*)d_in[20],
        (float*)d_out);
}

// round 16
// speedup vs baseline: 1.0737x; 1.0737x over previous
#include <cuda_runtime.h>
#include <math.h>

#define N_NODES   15000
#define N_EDGES   60000
#define EDGE_VOCAB 54
#define NODE_INDIM 64
#define EDGE_INDIM 32
#define H  32
#define EH 64
#define NBOND 4
#define NUM_STEPS 3
#define G   148                    // persistent blocks, 1 per SM
#define TPB 768
#define WPB (TPB / 32)
#define NWARPS (G * WPB)
#define CHUNK ((N_EDGES + G - 1) / G)

// ---------------- device scratch (no allocation allowed) -------------------
__device__ __align__(16) float  g_Wv[EDGE_VOCAB * H * H];
__device__ __align__(16) float  g_h[N_NODES * H];
__device__ __align__(16) float  g_agg[N_NODES * H];
__device__ __align__(16) float4 g_Wpk4[2 * 32 * 32];   // packed GRU weights
__device__ float g_p[N_NODES];
__device__ float g_q[N_NODES];
__device__ float g_nsum[N_NODES];
__device__ int   g_blockcnt[G * 64];
__device__ __align__(8) int2 g_ed[N_EDGES];   // {src | id<<16, dst}, sorted by id
__device__ int           g_bar_count = 0;
__device__ volatile int  g_bar_sense = 0;

// sense-reversing grid barrier; sense is read at kernel entry, so any number
// of barriers per launch is replay-safe.
__device__ __forceinline__ void grid_barrier(int* bsense) {
    __syncthreads();
    if (threadIdx.x == 0) {
        int my = *bsense ^ 1;
        __threadfence();
        if (atomicAdd(&g_bar_count, 1) == G - 1) {
            g_bar_count = 0;
            __threadfence();
            g_bar_sense = my;
        } else {
            while (g_bar_sense != my) { __nanosleep(32); }
        }
        __threadfence();
        *bsense = my;
    }
    __syncthreads();
}

__device__ __forceinline__ float sigmoidf_fast(float x) {
    return __fdividef(1.0f, 1.0f + __expf(-x));
}

__global__ void __launch_bounds__(TPB, 1)
k_fused(const int* __restrict__ node_ids, const int* __restrict__ edge_ids,
        const int* __restrict__ src, const int* __restrict__ dst,
        const float* __restrict__ node_table, const float* __restrict__ edge_table,
        const float* __restrict__ projW, const float* __restrict__ projb,
        const float* __restrict__ attn_w,
        const float* __restrict__ e1W1, const float* __restrict__ e1b1,
        const float* __restrict__ e1W2, const float* __restrict__ e1b2,
        const float* __restrict__ e2W1, const float* __restrict__ e2b1,
        const float* __restrict__ e2W2, const float* __restrict__ e2b2,
        const float* __restrict__ Wih, const float* __restrict__ Whh,
        const float* __restrict__ bih, const float* __restrict__ bhh,
        float* __restrict__ out) {
    __shared__ float S[NODE_INDIM * H];    // proj weights / wvocab tmp (8 KB)
    __shared__ int   SI[64];
    __shared__ int   bsense_sh;

    const int t    = threadIdx.x;
    const int b    = blockIdx.x;
    const int warp = t >> 5;
    const int lane = t & 31;
    const int gwarp = b * WPB + warp;

    if (t == 0) bsense_sh = g_bar_sense;   // adaptive sense: any parity OK
    __syncthreads();
    int bsense = bsense_sh;

    const int ebase = b * CHUNK;
    const int eend  = min(ebase + CHUNK, N_EDGES);

    // ================= phase 0: histogram + vocab W + GRU weight packing ===
    if (t < EDGE_VOCAB) SI[t] = 0;
    __syncthreads();
    for (int e = ebase + t; e < eend; e += TPB) atomicAdd(&SI[edge_ids[e]], 1);
    __syncthreads();
    if (t < EDGE_VOCAB) g_blockcnt[b * 64 + t] = SI[t];

    if (b < EDGE_VOCAB) {   // one block per vocab entry computes its W matrix
        const int v = b;
        const bool bond = (v < NBOND);
        const float* W1 = bond ? e1W1 : e2W1;
        const float* b1 = bond ? e1b1 : e2b1;
        const float* W2 = bond ? e1W2 : e2W2;
        const float* b2 = bond ? e1b2 : e2b2;
        float* ef = S;          // [32]
        float* z  = S + 32;     // [64]
        if (t < EDGE_INDIM) ef[t] = edge_table[v * EDGE_INDIM + t];
        __syncthreads();
        if (t < EH) {
            float acc = b1[t];
            #pragma unroll
            for (int i = 0; i < EDGE_INDIM; i++) acc += ef[i] * W1[t * EDGE_INDIM + i];
            z[t] = fmaxf(acc, 0.0f);
        }
        __syncthreads();
        for (int o = t; o < H * H; o += TPB) {
            float acc = b2[o];
            const float* w = W2 + o * EH;
            #pragma unroll
            for (int k = 0; k < EH; k++) acc += z[k] * w[k];
            g_Wv[v * H * H + o] = acc;
        }
    } else if (b == EDGE_VOCAB) {
        // pack GRU weights: g_Wpk4[m*1024 + k*32 + o] = {W[o][k], W[32+o][k], W[64+o][k], 0}
        for (int f = t; f < 2048; f += TPB) {
            int mm = f >> 10, r = f & 1023, k = r >> 5, o = r & 31;
            const float* Wsrc = mm ? Whh : Wih;
            g_Wpk4[f] = make_float4(Wsrc[o * H + k],
                                    Wsrc[(32 + o) * H + k],
                                    Wsrc[(64 + o) * H + k], 0.0f);
        }
    }
    grid_barrier(&bsense);                                     // B1

    // ====== redundant per-block scan: every block computes its own offsets =
    if (t < EDGE_VOCAB) {
        int tot = 0;
        for (int bb = 0; bb < G; bb++) tot += g_blockcnt[bb * 64 + t];
        SI[t] = tot;          // total size of bucket t
    }
    __syncthreads();
    if (t == 0) {
        int acc = 0;
        for (int v = 0; v < EDGE_VOCAB; v++) { int c = SI[v]; SI[v] = acc; acc += c; }
    }
    __syncthreads();
    if (t < EDGE_VOCAB) {
        int pre = 0;
        for (int bb = 0; bb < b; bb++) pre += g_blockcnt[bb * 64 + t];
        SI[t] = SI[t] + pre;   // this block's scatter cursor for bucket t
    }
    __syncthreads();

    // ================= phase 2: scatter (sort by vocab) + init h ===========
    for (int e = ebase + t; e < eend; e += TPB) {
        int id = edge_ids[e];
        int pos = atomicAdd(&SI[id], 1);
        g_ed[pos] = make_int2(src[e] | (id << 16), dst[e]);
    }
    // init h = relu(nf @ projW^T + b), attention dots, accumulator reset
    {
        for (int idx = t; idx < H * NODE_INDIM; idx += TPB) {
            int o = idx / NODE_INDIM, i = idx % NODE_INDIM;
            S[i * H + o] = projW[idx];
        }
        __syncthreads();
        float aw0 = attn_w[lane], aw1 = attn_w[H + lane];
        for (int v = gwarp; v < N_NODES; v += NWARPS) {
            int nid = node_ids[v];
            const float* nf = node_table + nid * NODE_INDIM;
            float v0 = nf[lane];
            float v1 = nf[lane + 32];
            float acc = projb[lane];
            #pragma unroll
            for (int i = 0; i < 32; i++)
                acc += __shfl_sync(0xffffffffu, v0, i) * S[i * H + lane];
            #pragma unroll
            for (int i = 0; i < 32; i++)
                acc += __shfl_sync(0xffffffffu, v1, i) * S[(i + 32) * H + lane];
            float hv = fmaxf(acc, 0.0f);
            g_h[v * H + lane] = hv;
            g_agg[v * H + lane] = 0.0f;
            float pv = hv * aw0;
            float qv = hv * aw1;
            #pragma unroll
            for (int off = 16; off; off >>= 1) {
                pv += __shfl_down_sync(0xffffffffu, pv, off);
                qv += __shfl_down_sync(0xffffffffu, qv, off);
            }
            if (lane == 0) { g_p[v] = pv; g_q[v] = qv; g_nsum[v] = 0.0f; }
        }
    }
    grid_barrier(&bsense);                                     // B2

    // ================= message passing steps ===============================
    const float b_i0 = bih[lane], b_i1 = bih[32 + lane], b_i2 = bih[64 + lane];
    const float b_h0 = bhh[lane], b_h1 = bhh[32 + lane], b_h2 = bhh[64 + lane];
    const float aw0 = attn_w[lane], aw1 = attn_w[H + lane];

    for (int step = 0; step < NUM_STEPS; step++) {
        // ---- edge phase: warp-per-edge, W in regs, 2-deep prefetch incl. h
        {
            int len = eend - ebase;
            int per = (len + WPB - 1) / WPB;
            int w0 = ebase + warp * per;
            int w1 = min(w0 + per, eend);
            int cached = -1;
            float Wr[32];
            if (w0 < w1) {
                // prefetch pipeline: descriptor, p/q, AND head of h row
                int2 ed = g_ed[w0];
                int sN = ed.x & 0xFFFF;
                float pn = g_p[sN];
                float qn = g_q[ed.y];
                const float4* h4n = (const float4*)(g_h + sN * H);
                float4 f0n = h4n[0], f1n = h4n[1];
                for (int pos = w0; pos < w1; pos++) {
                    int2 cur = ed;
                    float pc = pn, qc = qn;
                    const float4* h4 = h4n;
                    float4 f0 = f0n, f1 = f1n;
                    if (pos + 1 < w1) {
                        ed = g_ed[pos + 1];
                        sN = ed.x & 0xFFFF;
                        pn = g_p[sN];
                        qn = g_q[ed.y];
                        h4n = (const float4*)(g_h + sN * H);
                        f0n = h4n[0];
                        f1n = h4n[1];
                    }
                    int s  = cur.x & 0xFFFF;
                    int id = cur.x >> 16;
                    int d  = cur.y;
                    (void)s;
                    if (id != cached) {
                        cached = id;
                        const float* Wp = g_Wv + id * (H * H) + lane;
                        #pragma unroll
                        for (int k = 0; k < 32; k++) Wr[k] = Wp[k * 32];
                    }
                    float a = pc + qc;
                    a = (a > 0.0f) ? a : 0.01f * a;        // leaky_relu
                    float ex = __expf(a);                  // shift-free softmax
                    float a0 = 0.0f, a1 = 0.0f, a2 = 0.0f, a3 = 0.0f;
                    // ping-pong float4 stream; f0/f1 already prefetched
                    #pragma unroll
                    for (int j = 0; j < 8; j++) {
                        float4 c = (j & 1) ? f1 : f0;
                        if (j + 2 < 8) { if (j & 1) f1 = h4[j + 2]; else f0 = h4[j + 2]; }
                        a0 = fmaf(c.x, Wr[4 * j + 0], a0);
                        a1 = fmaf(c.y, Wr[4 * j + 1], a1);
                        a2 = fmaf(c.z, Wr[4 * j + 2], a2);
                        a3 = fmaf(c.w, Wr[4 * j + 3], a3);
                    }
                    float acc = ((a0 + a1) + (a2 + a3)) * ex;
                    atomicAdd(&g_agg[d * H + lane], acc);
                    if (lane == 0) atomicAdd(&g_nsum[d], ex);
                }
            }
        }
        grid_barrier(&bsense);                                 // B-edge (x3)

        // ---- GRU phase: 4 nodes per warp, packed float4 weights (L1)
        {
            const int last = (step == NUM_STEPS - 1);
            const float4* __restrict__ Wpk = g_Wpk4;
            for (int v0 = gwarp * 4; v0 < N_NODES; v0 += NWARPS * 4) {
                float m[4], hv[4];
                float gi[4][3], gh[4][3];
                #pragma unroll
                for (int j = 0; j < 4; j++) {
                    int v = min(v0 + j, N_NODES - 1);
                    float ns = g_nsum[v];
                    float inv = (ns > 0.0f) ? __fdividef(1.0f, ns) : 0.0f;
                    m[j]  = fmaxf(g_agg[v * H + lane] * inv, 0.0f);
                    hv[j] = g_h[v * H + lane];
                    gi[j][0] = b_i0; gi[j][1] = b_i1; gi[j][2] = b_i2;
                    gh[j][0] = b_h0; gh[j][1] = b_h1; gh[j][2] = b_h2;
                }
                #pragma unroll
                for (int k = 0; k < 32; k++) {
                    float4 wi = Wpk[k * 32 + lane];
                    float4 wh = Wpk[1024 + k * 32 + lane];
                    #pragma unroll
                    for (int j = 0; j < 4; j++) {
                        float mi = __shfl_sync(0xffffffffu, m[j], k);
                        float hi = __shfl_sync(0xffffffffu, hv[j], k);
                        gi[j][0] = fmaf(mi, wi.x, gi[j][0]);
                        gi[j][1] = fmaf(mi, wi.y, gi[j][1]);
                        gi[j][2] = fmaf(mi, wi.z, gi[j][2]);
                        gh[j][0] = fmaf(hi, wh.x, gh[j][0]);
                        gh[j][1] = fmaf(hi, wh.y, gh[j][1]);
                        gh[j][2] = fmaf(hi, wh.z, gh[j][2]);
                    }
                }
                #pragma unroll
                for (int j = 0; j < 4; j++) {
                    int v = v0 + j;
                    if (v >= N_NODES) break;
                    float r = sigmoidf_fast(gi[j][0] + gh[j][0]);
                    float z = sigmoidf_fast(gi[j][1] + gh[j][1]);
                    float n = tanhf(gi[j][2] + r * gh[j][2]);
                    float hnew = (1.0f - z) * n + z * hv[j];
                    if (last) {
                        out[v * H + lane] = hnew;
                    } else {
                        g_h[v * H + lane] = hnew;
                        g_agg[v * H + lane] = 0.0f;
                        float pv = hnew * aw0;
                        float qv = hnew * aw1;
                        #pragma unroll
                        for (int off = 16; off; off >>= 1) {
                            pv += __shfl_down_sync(0xffffffffu, pv, off);
                            qv += __shfl_down_sync(0xffffffffu, qv, off);
                        }
                        if (lane == 0) { g_p[v] = pv; g_q[v] = qv; g_nsum[v] = 0.0f; }
                    }
                }
            }
        }
        if (step < NUM_STEPS - 1) grid_barrier(&bsense);       // B-gru (x2)
    }
}

// ---------------- launch ----------------------------------------------------
extern "C" void kernel_launch(void* const* d_in, const int* in_sizes, int n_in,
                              void* d_out, int out_size) {
    k_fused<<<G, TPB>>>(
        (const int*)d_in[0], (const int*)d_in[1], (const int*)d_in[2],
        (const int*)d_in[3], (const float*)d_in[4], (const float*)d_in[5],
        (const float*)d_in[6], (const float*)d_in[7], (const float*)d_in[8],
        (const float*)d_in[9], (const float*)d_in[10], (const float*)d_in[11],
        (const float*)d_in[12], (const float*)d_in[13], (const float*)d_in[14],
        (const float*)d_in[15], (const float*)d_in[16], (const float*)d_in[17],
        (const float*)d_in[18], (const float*)d_in[19], (const float*)d_in[20],
        (float*)d_out);
}

// round 17
// speedup vs baseline: 1.1857x; 1.1043x over previous
#include <cuda_runtime.h>
#include <math.h>

#define N_NODES   15000
#define N_EDGES   60000
#define EDGE_VOCAB 54
#define NODE_INDIM 64
#define EDGE_INDIM 32
#define H  32
#define EH 64
#define NBOND 4
#define NUM_STEPS 3
#define G   148                    // persistent blocks, 1 per SM
#define GPAD 152                   // padded stride for int4 scan reads
#define TPB 768
#define WPB (TPB / 32)
#define NWARPS (G * WPB)
#define CHUNK ((N_EDGES + G - 1) / G)

// ---------------- device scratch (no allocation allowed) -------------------
__device__ __align__(16) float  g_Wv[EDGE_VOCAB * H * H];
__device__ __align__(16) float  g_h[N_NODES * H];
__device__ __align__(16) float  g_agg[N_NODES * H];
__device__ __align__(16) float4 g_Wpk4[2 * 32 * 32];   // packed GRU weights
__device__ float g_p[N_NODES];
__device__ float g_q[N_NODES];
__device__ float g_nsum[N_NODES];
__device__ __align__(16) int g_blockcnt[64 * GPAD];   // [vocab][block] transposed
__device__ __align__(8) int2 g_ed[N_EDGES];   // {src | id<<16, dst}, sorted by id
__device__ int           g_bar_count = 0;
__device__ volatile int  g_bar_sense = 0;

// sense-reversing grid barrier; sense is read at kernel entry, so any number
// of barriers per launch is replay-safe.
__device__ __forceinline__ void grid_barrier(int* bsense) {
    __syncthreads();
    if (threadIdx.x == 0) {
        int my = *bsense ^ 1;
        __threadfence();
        if (atomicAdd(&g_bar_count, 1) == G - 1) {
            g_bar_count = 0;
            __threadfence();
            g_bar_sense = my;
        } else {
            while (g_bar_sense != my) { __nanosleep(32); }
        }
        __threadfence();
        *bsense = my;
    }
    __syncthreads();
}

__device__ __forceinline__ float sigmoidf_fast(float x) {
    return __fdividef(1.0f, 1.0f + __expf(-x));
}

__global__ void __launch_bounds__(TPB, 1)
k_fused(const int* __restrict__ node_ids, const int* __restrict__ edge_ids,
        const int* __restrict__ src, const int* __restrict__ dst,
        const float* __restrict__ node_table, const float* __restrict__ edge_table,
        const float* __restrict__ projW, const float* __restrict__ projb,
        const float* __restrict__ attn_w,
        const float* __restrict__ e1W1, const float* __restrict__ e1b1,
        const float* __restrict__ e1W2, const float* __restrict__ e1b2,
        const float* __restrict__ e2W1, const float* __restrict__ e2b1,
        const float* __restrict__ e2W2, const float* __restrict__ e2b2,
        const float* __restrict__ Wih, const float* __restrict__ Whh,
        const float* __restrict__ bih, const float* __restrict__ bhh,
        float* __restrict__ out) {
    __shared__ float  S[NODE_INDIM * H];   // proj weights / wvocab tmp (8 KB)
    __shared__ int    SI[128];             // scan totals / prefixes / cursors
    __shared__ float4 sWpk[2048];          // GRU packed weights (32 KB, LDS.128)
    __shared__ int    bsense_sh;

    const int t    = threadIdx.x;
    const int b    = blockIdx.x;
    const int warp = t >> 5;
    const int lane = t & 31;
    const int gwarp = b * WPB + warp;

    if (t == 0) bsense_sh = g_bar_sense;   // adaptive sense: any parity OK
    __syncthreads();
    int bsense = bsense_sh;

    const int ebase = b * CHUNK;
    const int eend  = min(ebase + CHUNK, N_EDGES);

    // ================= phase 0: histogram + vocab W + GRU weight packing ===
    if (t < EDGE_VOCAB) SI[t] = 0;
    __syncthreads();
    for (int e = ebase + t; e < eend; e += TPB) atomicAdd(&SI[edge_ids[e]], 1);
    __syncthreads();
    if (t < EDGE_VOCAB) g_blockcnt[t * GPAD + b] = SI[t];

    if (b < EDGE_VOCAB) {   // one block per vocab entry computes its W matrix
        const int v = b;
        const bool bond = (v < NBOND);
        const float* W1 = bond ? e1W1 : e2W1;
        const float* b1 = bond ? e1b1 : e2b1;
        const float* W2 = bond ? e1W2 : e2W2;
        const float* b2 = bond ? e1b2 : e2b2;
        float* ef = S;          // [32]
        float* z  = S + 32;     // [64]
        if (t < EDGE_INDIM) ef[t] = edge_table[v * EDGE_INDIM + t];
        __syncthreads();
        if (t < EH) {
            float acc = b1[t];
            #pragma unroll
            for (int i = 0; i < EDGE_INDIM; i++) acc += ef[i] * W1[t * EDGE_INDIM + i];
            z[t] = fmaxf(acc, 0.0f);
        }
        __syncthreads();
        for (int o = t; o < H * H; o += TPB) {
            float acc = b2[o];
            const float* w = W2 + o * EH;
            #pragma unroll
            for (int k = 0; k < EH; k++) acc += z[k] * w[k];
            g_Wv[v * H * H + o] = acc;
        }
    } else if (b == EDGE_VOCAB) {
        // pack GRU weights: g_Wpk4[m*1024 + k*32 + o] = {W[o][k], W[32+o][k], W[64+o][k], 0}
        for (int f = t; f < 2048; f += TPB) {
            int mm = f >> 10, r = f & 1023, k = r >> 5, o = r & 31;
            const float* Wsrc = mm ? Whh : Wih;
            g_Wpk4[f] = make_float4(Wsrc[o * H + k],
                                    Wsrc[(32 + o) * H + k],
                                    Wsrc[(64 + o) * H + k], 0.0f);
        }
    }
    grid_barrier(&bsense);                                     // B1

    // copy packed GRU weights into smem once (persist across all steps)
    for (int f = t; f < 2048; f += TPB) sWpk[f] = g_Wpk4[f];

    // ====== vectorized redundant scan: int4 over transposed blockcnt =======
    if (t < EDGE_VOCAB) {
        const int4* bc = (const int4*)(g_blockcnt + t * GPAD);
        int tot = 0, pre = 0;
        #pragma unroll 4
        for (int i = 0; i < G / 4; i++) {       // 148/4 = 37 exact
            int4 c = bc[i];
            int bb = 4 * i;
            tot += c.x + c.y + c.z + c.w;
            pre += (bb + 0 < b ? c.x : 0) + (bb + 1 < b ? c.y : 0)
                 + (bb + 2 < b ? c.z : 0) + (bb + 3 < b ? c.w : 0);
        }
        SI[t] = tot;
        SI[64 + t] = pre;
    }
    __syncthreads();
    if (t == 0) {
        int acc = 0;
        for (int v = 0; v < EDGE_VOCAB; v++) { int c = SI[v]; SI[v] = acc; acc += c; }
    }
    __syncthreads();
    if (t < EDGE_VOCAB) SI[t] += SI[64 + t];   // this block's cursor for bucket t
    __syncthreads();

    // ================= phase 2: scatter (sort by vocab) + init h ===========
    for (int e = ebase + t; e < eend; e += TPB) {
        int id = edge_ids[e];
        int pos = atomicAdd(&SI[id], 1);
        g_ed[pos] = make_int2(src[e] | (id << 16), dst[e]);
    }
    // init h = relu(nf @ projW^T + b), attention dots, accumulator reset
    {
        for (int idx = t; idx < H * NODE_INDIM; idx += TPB) {
            int o = idx / NODE_INDIM, i = idx % NODE_INDIM;
            S[i * H + o] = projW[idx];
        }
        __syncthreads();
        float aw0 = attn_w[lane], aw1 = attn_w[H + lane];
        for (int v = gwarp; v < N_NODES; v += NWARPS) {
            int nid = node_ids[v];
            const float* nf = node_table + nid * NODE_INDIM;
            float v0 = nf[lane];
            float v1 = nf[lane + 32];
            float acc = projb[lane];
            #pragma unroll
            for (int i = 0; i < 32; i++)
                acc += __shfl_sync(0xffffffffu, v0, i) * S[i * H + lane];
            #pragma unroll
            for (int i = 0; i < 32; i++)
                acc += __shfl_sync(0xffffffffu, v1, i) * S[(i + 32) * H + lane];
            float hv = fmaxf(acc, 0.0f);
            g_h[v * H + lane] = hv;
            g_agg[v * H + lane] = 0.0f;
            float pv = hv * aw0;
            float qv = hv * aw1;
            #pragma unroll
            for (int off = 16; off; off >>= 1) {
                pv += __shfl_down_sync(0xffffffffu, pv, off);
                qv += __shfl_down_sync(0xffffffffu, qv, off);
            }
            if (lane == 0) { g_p[v] = pv; g_q[v] = qv; g_nsum[v] = 0.0f; }
        }
    }
    grid_barrier(&bsense);                                     // B2

    // ================= message passing steps ===============================
    const float b_i0 = bih[lane], b_i1 = bih[32 + lane], b_i2 = bih[64 + lane];
    const float b_h0 = bhh[lane], b_h1 = bhh[32 + lane], b_h2 = bhh[64 + lane];
    const float aw0 = attn_w[lane], aw1 = attn_w[H + lane];

    for (int step = 0; step < NUM_STEPS; step++) {
        // ---- edge phase: warp-per-edge, W in regs, 2-deep prefetch incl. h
        {
            int len = eend - ebase;
            int per = (len + WPB - 1) / WPB;
            int w0 = ebase + warp * per;
            int w1 = min(w0 + per, eend);
            int cached = -1;
            float Wr[32];
            if (w0 < w1) {
                // prefetch pipeline: descriptor, p/q, AND head of h row
                int2 ed = g_ed[w0];
                int sN = ed.x & 0xFFFF;
                float pn = g_p[sN];
                float qn = g_q[ed.y];
                const float4* h4n = (const float4*)(g_h + sN * H);
                float4 f0n = h4n[0], f1n = h4n[1];
                for (int pos = w0; pos < w1; pos++) {
                    int2 cur = ed;
                    float pc = pn, qc = qn;
                    const float4* h4 = h4n;
                    float4 f0 = f0n, f1 = f1n;
                    if (pos + 1 < w1) {
                        ed = g_ed[pos + 1];
                        sN = ed.x & 0xFFFF;
                        pn = g_p[sN];
                        qn = g_q[ed.y];
                        h4n = (const float4*)(g_h + sN * H);
                        f0n = h4n[0];
                        f1n = h4n[1];
                    }
                    int id = cur.x >> 16;
                    int d  = cur.y;
                    if (id != cached) {
                        cached = id;
                        const float* Wp = g_Wv + id * (H * H) + lane;
                        #pragma unroll
                        for (int k = 0; k < 32; k++) Wr[k] = Wp[k * 32];
                    }
                    float a = pc + qc;
                    a = (a > 0.0f) ? a : 0.01f * a;        // leaky_relu
                    float ex = __expf(a);                  // shift-free softmax
                    float a0 = 0.0f, a1 = 0.0f, a2 = 0.0f, a3 = 0.0f;
                    // ping-pong float4 stream; f0/f1 already prefetched
                    #pragma unroll
                    for (int j = 0; j < 8; j++) {
                        float4 c = (j & 1) ? f1 : f0;
                        if (j + 2 < 8) { if (j & 1) f1 = h4[j + 2]; else f0 = h4[j + 2]; }
                        a0 = fmaf(c.x, Wr[4 * j + 0], a0);
                        a1 = fmaf(c.y, Wr[4 * j + 1], a1);
                        a2 = fmaf(c.z, Wr[4 * j + 2], a2);
                        a3 = fmaf(c.w, Wr[4 * j + 3], a3);
                    }
                    float acc = ((a0 + a1) + (a2 + a3)) * ex;
                    atomicAdd(&g_agg[d * H + lane], acc);
                    if (lane == 0) atomicAdd(&g_nsum[d], ex);
                }
            }
        }
        grid_barrier(&bsense);                                 // B-edge (x3)

        // ---- GRU phase: 3 nodes per warp, weights from smem (LDS.128)
        {
            const int last = (step == NUM_STEPS - 1);
            for (int v0 = gwarp * 3; v0 < N_NODES; v0 += NWARPS * 3) {
                float m[3], hv[3];
                float gi[3][3], gh[3][3];
                #pragma unroll
                for (int j = 0; j < 3; j++) {
                    int v = min(v0 + j, N_NODES - 1);
                    float ns = g_nsum[v];
                    float inv = (ns > 0.0f) ? __fdividef(1.0f, ns) : 0.0f;
                    m[j]  = fmaxf(g_agg[v * H + lane] * inv, 0.0f);
                    hv[j] = g_h[v * H + lane];
                    gi[j][0] = b_i0; gi[j][1] = b_i1; gi[j][2] = b_i2;
                    gh[j][0] = b_h0; gh[j][1] = b_h1; gh[j][2] = b_h2;
                }
                #pragma unroll
                for (int k = 0; k < 32; k++) {
                    float4 wi = sWpk[k * 32 + lane];
                    float4 wh = sWpk[1024 + k * 32 + lane];
                    #pragma unroll
                    for (int j = 0; j < 3; j++) {
                        float mi = __shfl_sync(0xffffffffu, m[j], k);
                        float hi = __shfl_sync(0xffffffffu, hv[j], k);
                        gi[j][0] = fmaf(mi, wi.x, gi[j][0]);
                        gi[j][1] = fmaf(mi, wi.y, gi[j][1]);
                        gi[j][2] = fmaf(mi, wi.z, gi[j][2]);
                        gh[j][0] = fmaf(hi, wh.x, gh[j][0]);
                        gh[j][1] = fmaf(hi, wh.y, gh[j][1]);
                        gh[j][2] = fmaf(hi, wh.z, gh[j][2]);
                    }
                }
                #pragma unroll
                for (int j = 0; j < 3; j++) {
                    int v = v0 + j;
                    if (v >= N_NODES) break;
                    float r = sigmoidf_fast(gi[j][0] + gh[j][0]);
                    float z = sigmoidf_fast(gi[j][1] + gh[j][1]);
                    float n = tanhf(gi[j][2] + r * gh[j][2]);
                    float hnew = (1.0f - z) * n + z * hv[j];
                    if (last) {
                        out[v * H + lane] = hnew;
                    } else {
                        g_h[v * H + lane] = hnew;
                        g_agg[v * H + lane] = 0.0f;
                        float pv = hnew * aw0;
                        float qv = hnew * aw1;
                        #pragma unroll
                        for (int off = 16; off; off >>= 1) {
                            pv += __shfl_down_sync(0xffffffffu, pv, off);
                            qv += __shfl_down_sync(0xffffffffu, qv, off);
                        }
                        if (lane == 0) { g_p[v] = pv; g_q[v] = qv; g_nsum[v] = 0.0f; }
                    }
                }
            }
        }
        if (step < NUM_STEPS - 1) grid_barrier(&bsense);       // B-gru (x2)
    }
}

// ---------------- launch ----------------------------------------------------
extern "C" void kernel_launch(void* const* d_in, const int* in_sizes, int n_in,
                              void* d_out, int out_size) {
    k_fused<<<G, TPB>>>(
        (const int*)d_in[0], (const int*)d_in[1], (const int*)d_in[2],
        (const int*)d_in[3], (const float*)d_in[4], (const float*)d_in[5],
        (const float*)d_in[6], (const float*)d_in[7], (const float*)d_in[8],
        (const float*)d_in[9], (const float*)d_in[10], (const float*)d_in[11],
        (const float*)d_in[12], (const float*)d_in[13], (const float*)d_in[14],
        (const float*)d_in[15], (const float*)d_in[16], (const float*)d_in[17],
        (const float*)d_in[18], (const float*)d_in[19], (const float*)d_in[20],
        (float*)d_out);
}